// round 5
// baseline (speedup 1.0000x reference)
#include <cuda_runtime.h>
#include <cuda_bf16.h>
#include <cstdint>

// Problem constants (fixed by reference):
//   g: (32, 16, 2048, 3) fp32, ar_phi: (3,3), ar_eta: (3,), ar_c: (3,)
//   P=3, KMAX=5 (11 windings), output: (32,) fp32
#define N_MC      32
#define N_SAMP    16
#define T_LEN     2048
#define TPRIME    2044                   // T - 1 - P
#define ROW_ELEMS (T_LEN * 3)            // 6144 floats
#define ROW_VEC4  (ROW_ELEMS / 4)        // 1536 float4s per row

#define CLUSTER   8                      // CTAs per cluster = per output m
#define GRID      (N_MC * CLUSTER)       // 256 CTAs, single wave
#define BLOCK     512                    // 2 sample-groups x 256 threads
#define CHUNK     8                      // t-outputs per thread
#define NWARPS    (BLOCK / 32)           // 16

#define PI_F      3.14159265358979323846f
#define TWO_PI_F  6.28318530717958647693f
#define INV_2PI_F 0.15915494309189533577f

// Torus logmap, cheap form: x - 2*pi*rint(x/2pi). Matches mod(x+pi,2pi)-pi
// everywhere except exact half-period boundaries (measure zero in fp32 data).
__device__ __forceinline__ float wrapf(float x) {
    return fmaf(-rintf(x * INV_2PI_F), TWO_PI_F, x);
}

__device__ __forceinline__ uint32_t smem_u32(const void* p) {
    uint32_t a;
    asm("{ .reg .u64 t; cvta.to.shared.u64 t, %1; cvt.u32.u64 %0, t; }"
        : "=r"(a) : "l"(p));
    return a;
}

__global__ __launch_bounds__(BLOCK) __cluster_dims__(CLUSTER, 1, 1)
void arp_cluster_kernel(const float* __restrict__ g,
                        const float* __restrict__ ar_phi,
                        const float* __restrict__ ar_eta,
                        const float* __restrict__ ar_c,
                        float* __restrict__ out) {
    __shared__ float sred[3][NWARPS];
    __shared__ float slots[CLUSTER][3];   // leader CTA collects per-rank sums

    const int tid   = threadIdx.x;
    const int inner = tid & 255;          // position within sample-group
    const int sid   = tid >> 8;           // which of this CTA's 2 samples
    const int m     = blockIdx.x / CLUSTER;
    uint32_t rank;
    asm("mov.u32 %0, %%cluster_ctarank;" : "=r"(rank));

    // Small params (L1-cached broadcast loads).
    float ph[3][3], cc[3];
#pragma unroll
    for (int d = 0; d < 3; d++) {
        ph[d][0] = __ldg(&ar_phi[d * 3 + 0]);
        ph[d][1] = __ldg(&ar_phi[d * 3 + 1]);
        ph[d][2] = __ldg(&ar_phi[d * 3 + 2]);
        cc[d]    = __ldg(&ar_c[d]);
    }

    // ---- One sample-row per thread-group: angles t0..t0+11, all 3 dims
    // = 9 consecutive float4s (3*t0 divisible by 4 since t0 % 8 == 0).
    const int row  = m * N_SAMP + (int)rank * 2 + sid;
    const int t0   = inner * CHUNK;
    const int base = (3 * t0) >> 2;
    const float4* g4 = reinterpret_cast<const float4*>(g)
                     + (size_t)row * ROW_VEC4;
    float f[36];
#pragma unroll
    for (int k = 0; k < 9; k++) {
        int idx = base + k;
        if (idx > ROW_VEC4 - 1) idx = ROW_VEC4 - 1;   // tail clamp (unused data)
        float4 v = __ldg(&g4[idx]);
        f[4 * k + 0] = v.x; f[4 * k + 1] = v.y;
        f[4 * k + 2] = v.z; f[4 * k + 3] = v.w;
    }

    // ---- AR(3) on wrapped first-diffs; each dx computed exactly once.
    float acc[3];
#pragma unroll
    for (int d = 0; d < 3; d++) {
        float dx[CHUNK + 3];
#pragma unroll
        for (int j = 0; j < CHUNK + 3; j++)
            dx[j] = wrapf(f[3 * (j + 1) + d] - f[3 * j + d]);
        float ss = 0.f;
#pragma unroll
        for (int j = 0; j < CHUNK; j++) {
            float dyv = dx[j + 3] - (ph[d][0] * dx[j + 2]
                                   + ph[d][1] * dx[j + 1]
                                   + ph[d][2] * dx[j]);
            float u = dyv - cc[d];
            if (t0 + j < TPRIME) ss = fmaf(u, u, ss);
        }
        acc[d] = ss;
    }

    // ---- Warp reduce, then 16-warp fold (both sample-groups sum together:
    // same m).
#pragma unroll
    for (int off = 16; off; off >>= 1)
#pragma unroll
        for (int d = 0; d < 3; d++)
            acc[d] += __shfl_xor_sync(0xffffffffu, acc[d], off);

    const int lane = tid & 31;
    const int warp = tid >> 5;
    if (lane == 0)
#pragma unroll
        for (int d = 0; d < 3; d++) sred[d][warp] = acc[d];
    __syncthreads();

    // ---- tid0 pushes this CTA's 3 sums into the LEADER CTA's slots via DSMEM.
    if (tid == 0) {
        float S[3];
#pragma unroll
        for (int d = 0; d < 3; d++) {
            float v = sred[d][0];
#pragma unroll
            for (int w = 1; w < NWARPS; w++) v += sred[d][w];
            S[d] = v;
        }
        uint32_t laddr = smem_u32(&slots[rank][0]);   // same layout in every CTA
        uint32_t raddr;
        asm volatile("mapa.shared::cluster.u32 %0, %1, %2;"
                     : "=r"(raddr) : "r"(laddr), "r"(0u));   // -> leader (rank 0)
#pragma unroll
        for (int d = 0; d < 3; d++)
            asm volatile("st.shared::cluster.f32 [%0], %1;"
                         :: "r"(raddr + 4u * d), "f"(S[d]) : "memory");
    }

    // Cluster barrier: release DSMEM stores, then leader may read.
    asm volatile("barrier.cluster.arrive.aligned;" ::: "memory");
    asm volatile("barrier.cluster.wait.aligned;" ::: "memory");

    // ---- Leader CTA: fold 8 ranks + closed-form winding constant, write out[m].
    //   sum_{k=-5..5} winding log-density collapses (sum k = 0, sum k^2 = 110) to
    //   -5.5*u^2/var - 220*pi^2/var - 11*log(scale) - 5.5*log(2*pi) per (t,d).
    // fp32 throughout: abs error ~1e4 vs tolerance ~8.5e7.
    if (rank == 0 && tid == 0) {
        float res = 0.f;
#pragma unroll
        for (int d = 0; d < 3; d++) {
            float Sd = 0.f;
#pragma unroll
            for (int r = 0; r < CLUSTER; r++) Sd += slots[r][d];
            float e   = fabsf(ar_eta[d]);            // scale = sqrt(eta^2)
            float var = e * e;
            float C = -220.f * (PI_F * PI_F) / var - 11.f * logf(e)
                      - 5.5f * logf(TWO_PI_F);
            res += -5.5f * Sd / var + (float)(N_SAMP * TPRIME) * C;
        }
        out[m] = res;
    }
}

extern "C" void kernel_launch(void* const* d_in, const int* in_sizes, int n_in,
                              void* d_out, int out_size) {
    const float* g      = (const float*)d_in[0];
    const float* ar_phi = (const float*)d_in[1];
    const float* ar_eta = (const float*)d_in[2];
    const float* ar_c   = (const float*)d_in[3];
    float* out = (float*)d_out;

    arp_cluster_kernel<<<GRID, BLOCK>>>(g, ar_phi, ar_eta, ar_c, out);
}